// round 1
// baseline (speedup 1.0000x reference)
#include <cuda_runtime.h>
#include <cstdint>

// Problem shapes (fixed by the reference)
#define Bq 8
#define Sq 8192
#define Nq 16
#define Dq 64
#define Mq 64
#define NCHUNK 8
#define SSUB (Sq / NCHUNK)   // 1024 s-steps per block
#define TILE 8               // s-rows staged in smem per sync

#define V_ELEMS   (Bq * Nq * Mq)            // 8192
#define SST_ELEMS (Bq * Nq * Mq * Dq)       // 524288
#define Z_ELEMS   (Bq * Nq * Dq)            // 8192

// Scratch for deterministic two-phase reduction (device globals: allowed)
__device__ float g_sst_part[Bq * Nq * NCHUNK * Mq * Dq];  // ~16.8 MB
__device__ float g_z_part[Bq * Nq * NCHUNK * Dq];

__device__ __forceinline__ float elu1(float x) {
    // elu(x)+1 = x+1 (x>0) else exp(x)
    return x > 0.0f ? x + 1.0f : __expf(x);
}

// Packed f32x2 FMA (Blackwell-only PTX; doubles FFMA throughput)
__device__ __forceinline__ uint64_t fma2(uint64_t a, uint64_t b, uint64_t c) {
    uint64_t d;
    asm("fma.rn.f32x2 %0, %1, %2, %3;" : "=l"(d) : "l"(a), "l"(b), "l"(c));
    return d;
}
__device__ __forceinline__ uint64_t splat2(float x) {
    uint64_t d;
    asm("mov.b64 %0, {%1, %2};" : "=l"(d) : "f"(x), "f"(x));
    return d;
}

// ---------------------------------------------------------------------------
// Phase 1: partial Sst[bn] (64x64) and Z[bn] (64) per s-chunk.
// Block = 256 threads, each owns a 4(m) x 4(d) register tile as 8 f32x2 accs.
// ---------------------------------------------------------------------------
__global__ void __launch_bounds__(256) rcla_phase1(
    const float* __restrict__ key,     // [B,S,N,D]
    const float* __restrict__ value,   // [B,S,N,M]
    const int* __restrict__ key_mask)  // [B,S] as 32-bit words, nonzero = True
{
    const int bn = blockIdx.x;           // 0..127
    const int c  = blockIdx.y;           // 0..7
    const int b  = bn >> 4;
    const int n  = bn & 15;

    __shared__ float ks[TILE][Dq];
    __shared__ float vs[TILE][Mq];

    const int tid = threadIdx.x;
    const int tm  = (tid >> 4) << 2;     // 0,4,...,60
    const int td  = (tid & 15) << 2;     // 0,4,...,60

    uint64_t acc[4][2];
#pragma unroll
    for (int i = 0; i < 4; i++) { acc[i][0] = 0ull; acc[i][1] = 0ull; }
    float zacc = 0.0f;

    const int s0 = c * SSUB;
    const float* kbase = key   + ((size_t)b * Sq * Nq + n) * Dq;
    const float* vbase = value + ((size_t)b * Sq * Nq + n) * Mq;

    // loader mapping: 8 rows x 32 cols; cols 0..15 -> K float4, 16..31 -> V float4
    const int lrow  = tid >> 5;
    const int lcol  = tid & 31;
    const bool isK  = lcol < 16;
    const int loff  = (lcol & 15) << 2;

    for (int t = 0; t < SSUB; t += TILE) {
        const int s = s0 + t + lrow;
        if (isK) {
            float4 kv = *(const float4*)(kbase + (size_t)s * (Nq * Dq) + loff);
            const float mm = key_mask[b * Sq + s] ? 0.0f : 1.0f;
            float4 r;
            r.x = mm * elu1(kv.x);
            r.y = mm * elu1(kv.y);
            r.z = mm * elu1(kv.z);
            r.w = mm * elu1(kv.w);
            *(float4*)&ks[lrow][loff] = r;
        } else {
            *(float4*)&vs[lrow][loff] =
                *(const float4*)(vbase + (size_t)s * (Nq * Mq) + loff);
        }
        __syncthreads();

#pragma unroll
        for (int r = 0; r < TILE; r++) {
            const uint64_t k01 = *(const uint64_t*)&ks[r][td];
            const uint64_t k23 = *(const uint64_t*)&ks[r][td + 2];
            const float4 v4 = *(const float4*)&vs[r][tm];
            uint64_t vv;
            vv = splat2(v4.x);
            acc[0][0] = fma2(vv, k01, acc[0][0]);
            acc[0][1] = fma2(vv, k23, acc[0][1]);
            vv = splat2(v4.y);
            acc[1][0] = fma2(vv, k01, acc[1][0]);
            acc[1][1] = fma2(vv, k23, acc[1][1]);
            vv = splat2(v4.z);
            acc[2][0] = fma2(vv, k01, acc[2][0]);
            acc[2][1] = fma2(vv, k23, acc[2][1]);
            vv = splat2(v4.w);
            acc[3][0] = fma2(vv, k01, acc[3][0]);
            acc[3][1] = fma2(vv, k23, acc[3][1]);
        }
        if (tid < Dq) {
#pragma unroll
            for (int r = 0; r < TILE; r++) zacc += ks[r][tid];
        }
        __syncthreads();
    }

    // write partials
    float* outs = g_sst_part + ((size_t)bn * NCHUNK + c) * (Mq * Dq);
#pragma unroll
    for (int i = 0; i < 4; i++) {
#pragma unroll
        for (int j = 0; j < 2; j++) {
            // little-endian: low float = d=td+2j, high = d=td+2j+1
            *(uint64_t*)&outs[(tm + i) * Dq + td + 2 * j] = acc[i][j];
        }
    }
    if (tid < Dq) {
        g_z_part[((size_t)bn * NCHUNK + c) * Dq + tid] = zacc;
    }
}

// ---------------------------------------------------------------------------
// Phase 2: deterministic chunk reduction + V epilogue. One block per (b,n).
// ---------------------------------------------------------------------------
__global__ void __launch_bounds__(256) rcla_phase2(
    const float* __restrict__ query,  // [B,N,D]
    float* __restrict__ outV,         // [B,N,M]
    float* __restrict__ outS,         // [B,N,M,D]
    float* __restrict__ outZ)         // [B,N,D]
{
    const int bn = blockIdx.x;
    const int tid = threadIdx.x;

    __shared__ float sst[Mq * Dq];    // 16 KB
    __shared__ float qs[Dq];
    __shared__ float prod[Dq];
    __shared__ float sinv;

    const float* base = g_sst_part + (size_t)bn * NCHUNK * (Mq * Dq);
    for (int e = tid; e < Mq * Dq; e += 256) {
        float sum = 0.0f;
#pragma unroll
        for (int c = 0; c < NCHUNK; c++) sum += base[c * (Mq * Dq) + e];
        sst[e] = sum;
        outS[(size_t)bn * (Mq * Dq) + e] = sum;
    }
    if (tid < Dq) {
        float zs = 0.0f;
#pragma unroll
        for (int c = 0; c < NCHUNK; c++)
            zs += g_z_part[((size_t)bn * NCHUNK + c) * Dq + tid];
        outZ[bn * Dq + tid] = zs;
        const float q = elu1(query[bn * Dq + tid]);
        qs[tid] = q;
        prod[tid] = q * zs;
    }
    __syncthreads();
    if (tid == 0) {
        float s = 0.0f;
#pragma unroll
        for (int d = 0; d < Dq; d++) s += prod[d];
        sinv = 1.0f / (s + 1e-6f);
    }
    __syncthreads();
    if (tid < Mq) {
        float v = 0.0f;
#pragma unroll
        for (int d = 0; d < Dq; d++) v += qs[d] * sst[tid * Dq + d];
        outV[bn * Mq + tid] = v * sinv;
    }
}

// ---------------------------------------------------------------------------
extern "C" void kernel_launch(void* const* d_in, const int* in_sizes, int n_in,
                              void* d_out, int out_size)
{
    const float* query = (const float*)d_in[0];
    const float* key   = (const float*)d_in[1];
    const float* value = (const float*)d_in[2];
    const int*   mask  = (const int*)d_in[3];

    float* out  = (float*)d_out;
    float* outV = out;                        // [B,N,M]     = 8192
    float* outS = out + V_ELEMS;              // [B,N,M,D]   = 524288
    float* outZ = out + V_ELEMS + SST_ELEMS;  // [B,N,D]     = 8192

    rcla_phase1<<<dim3(Bq * Nq, NCHUNK), 256>>>(key, value, mask);
    rcla_phase2<<<Bq * Nq, 256>>>(query, outV, outS, outZ);
}

// round 3
// speedup vs baseline: 1.2686x; 1.2686x over previous
#include <cuda_runtime.h>
#include <cstdint>

// Problem shapes
#define Bq 8
#define Sq 8192
#define Nq 16
#define Dq 64
#define Mq 64
#define NCHUNK 8
#define SSUB (Sq / NCHUNK)   // 1024 s-steps per block
#define TILE 16              // s-rows staged per sync
#define NIT (SSUB / TILE)    // 64 iterations

#define V_ELEMS   (Bq * Nq * Mq)            // 8192
#define SST_ELEMS (Bq * Nq * Mq * Dq)       // 524288

// Scratch for deterministic two-phase reduction
__device__ float g_sst_part[Bq * Nq * NCHUNK * Mq * Dq];  // ~16.8 MB
__device__ float g_z_part[Bq * Nq * NCHUNK * Dq];

__device__ __forceinline__ float elu1(float x) {
    return x > 0.0f ? x + 1.0f : __expf(x);
}
__device__ __forceinline__ uint64_t fma2(uint64_t a, uint64_t b, uint64_t c) {
    uint64_t d;
    asm("fma.rn.f32x2 %0, %1, %2, %3;" : "=l"(d) : "l"(a), "l"(b), "l"(c));
    return d;
}
__device__ __forceinline__ uint64_t add2(uint64_t a, uint64_t b) {
    uint64_t d;
    asm("add.rn.f32x2 %0, %1, %2;" : "=l"(d) : "l"(a), "l"(b));
    return d;
}

struct SMem {
    float ks[2][TILE][Dq];        // 8 KB  (elu'd, masked K)
    float vd[2][TILE][2 * Mq];    // 16 KB (V duplicated: vd[2m]=vd[2m+1]=v[m])
};
// final cross-sgroup reduction reuses this storage (needs 16 KB <= 24 KB)

// ---------------------------------------------------------------------------
// Phase 1: per-chunk partial Sst[bn] (64x64) and Z[bn] (64).
// 256 threads = 2 s-groups x 128; each thread owns a 4(m) x 8(d) tile
// as 16 f32x2 accumulators. Inner loop: 4 LDS.128 + 16 FFMA2 per s-row.
// ---------------------------------------------------------------------------
__global__ void __launch_bounds__(256) rcla_phase1(
    const float* __restrict__ key,     // [B,S,N,D]
    const float* __restrict__ value,   // [B,S,N,M]
    const int* __restrict__ key_mask)  // [B,S], nonzero = masked
{
    __shared__ SMem sm;

    const int bn = blockIdx.x;     // 0..127
    const int c  = blockIdx.y;     // 0..7
    const int b  = bn >> 4;
    const int n  = bn & 15;
    const int tid = threadIdx.x;

    // ---- loader mapping: 16 rows x 16 threads; each thread loads 1 K-float4
    //      and 1 V-float4 per iteration ----
    const int lrow = tid >> 4;           // 0..15
    const int loff = (tid & 15) << 2;    // 0,4,...,60
    const int s0 = c * SSUB + lrow;
    const float* kptr = key   + (((size_t)b * Sq + s0) * Nq + n) * Dq + loff;
    const float* vptr = value + (((size_t)b * Sq + s0) * Nq + n) * Mq + loff;
    const int*   mptr = key_mask + b * Sq + s0;
    const size_t KSTR = (size_t)TILE * Nq * Dq;   // floats per iteration
    const size_t VSTR = (size_t)TILE * Nq * Mq;

    // ---- compute mapping ----
    const int sg = tid >> 7;             // 0/1: which half of the 16 rows
    const int t  = tid & 127;
    const int m0 = ((t >> 3) & 15) << 2; // 0,4,...,60
    const int d0 = (t & 7) << 3;         // 0,8,...,56

    uint64_t acc[4][4];                  // [mi][d-pair j]: (d0+2j, d0+2j+1)
#pragma unroll
    for (int i = 0; i < 4; i++)
#pragma unroll
        for (int j = 0; j < 4; j++) acc[i][j] = 0ull;
    float zacc = 0.0f;

    // prefetch iteration 0
    float4 kin = *(const float4*)kptr;
    float4 vin = *(const float4*)vptr;
    int    min_ = *mptr;

    for (int it = 0; it < NIT; it++) {
        const int buf = it & 1;

        // transform + stage current tile
        {
            const float mm = min_ ? 0.0f : 1.0f;
            float4 r;
            r.x = mm * elu1(kin.x);
            r.y = mm * elu1(kin.y);
            r.z = mm * elu1(kin.z);
            r.w = mm * elu1(kin.w);
            *(float4*)&sm.ks[buf][lrow][loff] = r;
            float4 va = make_float4(vin.x, vin.x, vin.y, vin.y);
            float4 vb = make_float4(vin.z, vin.z, vin.w, vin.w);
            *(float4*)&sm.vd[buf][lrow][2 * loff]     = va;
            *(float4*)&sm.vd[buf][lrow][2 * loff + 4] = vb;
        }

        // prefetch next tile (latency hidden behind this iteration's compute)
        kptr += KSTR; vptr += VSTR; mptr += TILE;
        if (it + 1 < NIT) {
            kin  = *(const float4*)kptr;
            vin  = *(const float4*)vptr;
            min_ = *mptr;
        }

        __syncthreads();   // staged tile visible; prev reads of this buf done

        // compute 8 rows of this half
#pragma unroll
        for (int r = 0; r < TILE / 2; r++) {
            const int row = (sg << 3) + r;
            const ulonglong2 kA = *(const ulonglong2*)&sm.ks[buf][row][d0];
            const ulonglong2 kB = *(const ulonglong2*)&sm.ks[buf][row][d0 + 4];
            const ulonglong2 vA = *(const ulonglong2*)&sm.vd[buf][row][2 * m0];
            const ulonglong2 vB = *(const ulonglong2*)&sm.vd[buf][row][2 * m0 + 4];
            acc[0][0] = fma2(vA.x, kA.x, acc[0][0]);
            acc[0][1] = fma2(vA.x, kA.y, acc[0][1]);
            acc[0][2] = fma2(vA.x, kB.x, acc[0][2]);
            acc[0][3] = fma2(vA.x, kB.y, acc[0][3]);
            acc[1][0] = fma2(vA.y, kA.x, acc[1][0]);
            acc[1][1] = fma2(vA.y, kA.y, acc[1][1]);
            acc[1][2] = fma2(vA.y, kB.x, acc[1][2]);
            acc[1][3] = fma2(vA.y, kB.y, acc[1][3]);
            acc[2][0] = fma2(vB.x, kA.x, acc[2][0]);
            acc[2][1] = fma2(vB.x, kA.y, acc[2][1]);
            acc[2][2] = fma2(vB.x, kB.x, acc[2][2]);
            acc[2][3] = fma2(vB.x, kB.y, acc[2][3]);
            acc[3][0] = fma2(vB.y, kA.x, acc[3][0]);
            acc[3][1] = fma2(vB.y, kA.y, acc[3][1]);
            acc[3][2] = fma2(vB.y, kB.x, acc[3][2]);
            acc[3][3] = fma2(vB.y, kB.y, acc[3][3]);
        }

        // Z column sums (64 threads cover all 16 rows)
        if (tid < Dq) {
#pragma unroll
            for (int r = 0; r < TILE; r++) zacc += sm.ks[buf][r][tid];
        }
    }

    // ---- cross-sgroup reduction in smem, then write partials ----
    __syncthreads();
    uint64_t* scratch = (uint64_t*)&sm;   // 128 threads x 16 u64 = 16 KB
    if (sg == 1) {
#pragma unroll
        for (int i = 0; i < 4; i++)
#pragma unroll
            for (int j = 0; j < 4; j++)
                scratch[t * 16 + i * 4 + j] = acc[i][j];
    }
    __syncthreads();
    if (sg == 0) {
        float* outs = g_sst_part + ((size_t)bn * NCHUNK + c) * (Mq * Dq);
#pragma unroll
        for (int i = 0; i < 4; i++) {
#pragma unroll
            for (int j = 0; j < 4; j++)
                acc[i][j] = add2(acc[i][j], scratch[t * 16 + i * 4 + j]);
            ulonglong2 lo, hi;
            lo.x = acc[i][0]; lo.y = acc[i][1];
            hi.x = acc[i][2]; hi.y = acc[i][3];
            *(ulonglong2*)&outs[(m0 + i) * Dq + d0]     = lo;
            *(ulonglong2*)&outs[(m0 + i) * Dq + d0 + 4] = hi;
        }
    }
    if (tid < Dq) {
        g_z_part[((size_t)bn * NCHUNK + c) * Dq + tid] = zacc;
    }
}

// ---------------------------------------------------------------------------
// Phase 2: deterministic chunk reduction + V epilogue. One block per (b,n).
// ---------------------------------------------------------------------------
__global__ void __launch_bounds__(256) rcla_phase2(
    const float* __restrict__ query,  // [B,N,D]
    float* __restrict__ outV,         // [B,N,M]
    float* __restrict__ outS,         // [B,N,M,D]
    float* __restrict__ outZ)         // [B,N,D]
{
    const int bn = blockIdx.x;
    const int tid = threadIdx.x;

    __shared__ float sst[Mq * Dq];
    __shared__ float qs[Dq];
    __shared__ float prod[Dq];
    __shared__ float sinv;

    const float* base = g_sst_part + (size_t)bn * NCHUNK * (Mq * Dq);
    for (int e = tid; e < Mq * Dq; e += 256) {
        float sum = 0.0f;
#pragma unroll
        for (int c = 0; c < NCHUNK; c++) sum += base[c * (Mq * Dq) + e];
        sst[e] = sum;
        outS[(size_t)bn * (Mq * Dq) + e] = sum;
    }
    if (tid < Dq) {
        float zs = 0.0f;
#pragma unroll
        for (int c = 0; c < NCHUNK; c++)
            zs += g_z_part[((size_t)bn * NCHUNK + c) * Dq + tid];
        outZ[bn * Dq + tid] = zs;
        const float q = elu1(query[bn * Dq + tid]);
        qs[tid] = q;
        prod[tid] = q * zs;
    }
    __syncthreads();
    if (tid == 0) {
        float s = 0.0f;
#pragma unroll
        for (int d = 0; d < Dq; d++) s += prod[d];
        sinv = 1.0f / (s + 1e-6f);
    }
    __syncthreads();
    if (tid < Mq) {
        float v = 0.0f;
#pragma unroll
        for (int d = 0; d < Dq; d++) v += qs[d] * sst[tid * Dq + d];
        outV[bn * Mq + tid] = v * sinv;
    }
}

// ---------------------------------------------------------------------------
extern "C" void kernel_launch(void* const* d_in, const int* in_sizes, int n_in,
                              void* d_out, int out_size)
{
    const float* query = (const float*)d_in[0];
    const float* key   = (const float*)d_in[1];
    const float* value = (const float*)d_in[2];
    const int*   mask  = (const int*)d_in[3];

    float* out  = (float*)d_out;
    float* outV = out;                        // [B,N,M]
    float* outS = out + V_ELEMS;              // [B,N,M,D]
    float* outZ = out + V_ELEMS + SST_ELEMS;  // [B,N,D]

    rcla_phase1<<<dim3(Bq * Nq, NCHUNK), 256>>>(key, value, mask);
    rcla_phase2<<<Bq * Nq, 256>>>(query, outV, outS, outZ);
}